// round 6
// baseline (speedup 1.0000x reference)
#include <cuda_runtime.h>
#include <cstdint>
#include <cstddef>

#define Mdim 128
#define Ndim 64
#define Edim 32
#define Sdim 512
#define Bdim 8192

typedef unsigned long long ull;

// ---------------- scratch (no allocation allowed) ----------------
__device__ float g_w[Bdim * Edim];   // expert weights: [b*32 + e]

// ---------------- packed f32x2 helpers (sm_103a) ----------------
__device__ __forceinline__ void fma2(ull& acc, ull a, ull b)
{
    asm("fma.rn.f32x2 %0, %1, %2, %3;" : "=l"(acc) : "l"(a), "l"(b), "l"(acc));
}
__device__ __forceinline__ ull bcast2(float x)
{
    ull r;
    asm("mov.b64 %0, {%1, %1};" : "=l"(r) : "f"(x));
    return r;
}
__device__ __forceinline__ float2 unpack2(ull v)
{
    float2 f;
    asm("mov.b64 {%0, %1}, %2;" : "=f"(f.x), "=f"(f.y) : "l"(v));
    return f;
}

// ---------------- Kernel 0: zero the output (atomics accumulate into it) ----------------
__global__ void k_zero(float* __restrict__ out)
{
    int idx = blockIdx.x * blockDim.x + threadIdx.x;
    reinterpret_cast<float4*>(out)[idx] = make_float4(0.f, 0.f, 0.f, 0.f);
}

// ---------------- Kernel A: fused z_cur + streaming online-softmax attention
// ----------------           + conv-emb + MLP + expert softmax ----------------
#define K2_WARPS 8
#define CHUNK 8

struct OnlineState {
    float mrun, denom, pprev;
    float c0x, c0y, c1x, c1y;
};

__device__ __forceinline__ void row_proc(const float2 v, float zcx, float zcy,
                                         float invT1, OnlineState& st)
{
    float dd = fabsf(v.x - zcx) + fabsf(v.y - zcy);
    dd += __shfl_xor_sync(0xffffffffu, dd, 16);
    dd += __shfl_xor_sync(0xffffffffu, dd, 8);
    dd += __shfl_xor_sync(0xffffffffu, dd, 4);
    dd += __shfl_xor_sync(0xffffffffu, dd, 2);
    dd += __shfl_xor_sync(0xffffffffu, dd, 1);
    float logit = -dd * invT1;
    if (logit > st.mrun) {
        float s = __expf(st.mrun - logit);
        st.denom *= s; st.c0x *= s; st.c0y *= s; st.c1x *= s; st.c1y *= s; st.pprev *= s;
        st.mrun = logit;
    }
    float pw = __expf(logit - st.mrun);
    st.denom += pw;
    st.c0x = fmaf(pw, v.x, st.c0x);       st.c0y = fmaf(pw, v.y, st.c0y);
    st.c1x = fmaf(st.pprev, v.x, st.c1x); st.c1y = fmaf(st.pprev, v.y, st.c1y);
    st.pprev = pw;
}

__device__ __forceinline__ void load_chunk(float2* buf, const float2* p, size_t TSTEP, int cidx)
{
    const float2* q = p + (size_t)cidx * (size_t)CHUNK * TSTEP;
    #pragma unroll
    for (int r = 0; r < CHUNK; ++r) buf[r] = __ldcs(q + (size_t)r * TSTEP);
}

__device__ __forceinline__ void proc_chunk(const float2* buf, float zcx, float zcy,
                                           float invT1, OnlineState& st)
{
    #pragma unroll
    for (int r = 0; r < CHUNK; ++r) row_proc(buf[r], zcx, zcy, invT1, st);
}

__global__ __launch_bounds__(256, 3)
void k_attn(const float* __restrict__ ctx, const float* __restrict__ z,
            const float* __restrict__ noise, const float* __restrict__ Dm,
            const float* __restrict__ sigma_g,
            const float* __restrict__ conv_w, const float* __restrict__ conv_b,
            const float* __restrict__ temp1,
            const float* __restrict__ W1, const float* __restrict__ b1,
            const float* __restrict__ W2, const float* __restrict__ b2,
            const float* __restrict__ temp2)
{
    __shared__ float W1s[192 * 32];          // transposed [j][e]   24 KB
    __shared__ float W2s[32 * 32];           // transposed [j][e]    4 KB
    __shared__ float scomb[K2_WARPS][194];   // per-warp work        6.2 KB
    __shared__ float zs[Mdim][8];            // z[m][bb]             4 KB
    __shared__ float zcs[8][66];             // z_cur[bb][i]         2.1 KB

    int tid = threadIdx.x;
    int b0 = blockIdx.x * K2_WARPS;

    // ---- stage z tile [128 x 8] ----
    #pragma unroll
    for (int r = 0; r < 4; ++r) {
        int idx = tid + r * 256;
        int m = idx >> 3, bb = idx & 7;
        zs[m][bb] = z[(size_t)m * Bdim + b0 + bb];
    }
    // ---- stage MLP weights (transposed) ----
    for (int t = tid; t < 192 * 32; t += 256) {
        int e = t / 192, j = t % 192;
        W1s[j * 32 + e] = W1[t];
    }
    for (int t = tid; t < 32 * 32; t += 256) {
        int e = t / 32, j = t % 32;
        W2s[j * 32 + e] = W2[t];
    }
    __syncthreads();

    // ---- fused z_cur: zc[i][bb] = sigma[i]*noise[i,b] + sum_m D[i,m] z[m,b] ----
    {
        int i = tid >> 2;                    // 0..63
        int bb0 = (tid & 3) * 2;             // 0,2,4,6
        float a0 = sigma_g[i] * noise[(size_t)i * Bdim + b0 + bb0];
        float a1 = sigma_g[i] * noise[(size_t)i * Bdim + b0 + bb0 + 1];
        const float* drow = Dm + i * Mdim;
        #pragma unroll 4
        for (int m = 0; m < Mdim; ++m) {
            float d = __ldg(drow + m);
            float2 zz = *reinterpret_cast<const float2*>(&zs[m][bb0]);
            a0 = fmaf(d, zz.x, a0);
            a1 = fmaf(d, zz.y, a1);
        }
        zcs[bb0][i] = a0;
        zcs[bb0 + 1][i] = a1;
    }
    __syncthreads();

    int warp = tid >> 5, lane = tid & 31;
    int b = b0 + warp;

    float invT1 = 1.0f / fabsf(temp1[0]);
    float invT2 = 1.0f / fabsf(temp2[0]);

    float2 zc2 = *reinterpret_cast<const float2*>(&zcs[warp][2 * lane]);
    float zcx = zc2.x, zcy = zc2.y;

    const float2* p = reinterpret_cast<const float2*>(ctx) + (size_t)b * (Ndim / 2) + lane;
    const size_t TSTEP = (size_t)Bdim * (Ndim / 2);  // float2 per seq step

    OnlineState st;
    st.mrun = -1e30f; st.denom = 0.f; st.pprev = 0.f;
    st.c0x = 0.f; st.c0y = 0.f; st.c1x = 0.f; st.c1y = 0.f;
    float2 buf0[CHUNK], buf1[CHUNK];

    load_chunk(buf0, p, TSTEP, 0);
    for (int cc = 0; cc < 62; cc += 2) {
        load_chunk(buf1, p, TSTEP, cc + 1);
        proc_chunk(buf0, zcx, zcy, invT1, st);
        load_chunk(buf0, p, TSTEP, cc + 2);
        proc_chunk(buf1, zcx, zcy, invT1, st);
    }
    load_chunk(buf1, p, TSTEP, 63);
    proc_chunk(buf0, zcx, zcy, invT1, st);   // chunk 62 (rows 496..503)
    // chunk 63: rows 504..510 normal, row 511 only feeds c1 (shifted tap)
    #pragma unroll
    for (int r = 0; r < CHUNK - 1; ++r) row_proc(buf1[r], zcx, zcy, invT1, st);
    {
        float2 v = buf1[CHUNK - 1];
        st.c1x = fmaf(st.pprev, v.x, st.c1x);
        st.c1y = fmaf(st.pprev, v.y, st.c1y);
    }

    float rinv = 1.0f / st.denom;
    float* sc = scomb[warp];
    sc[2 * lane]      = st.c0x * rinv;  sc[2 * lane + 1]      = st.c0y * rinv;
    sc[64 + 2 * lane] = st.c1x * rinv;  sc[64 + 2 * lane + 1] = st.c1y * rinv;
    __syncwarp();

    // emb[o] = conv_b[o] + sum_i cw0[o,i]*c0[i] + cw1[o,i]*c1[i]
    int o0 = 2 * lane, o1 = 2 * lane + 1;
    float e0 = conv_b[o0], e1 = conv_b[o1];
    const float* cwA = conv_w + (size_t)o0 * 128;   // conv_w[o][i][tap]
    const float* cwB = conv_w + (size_t)o1 * 128;
    #pragma unroll 8
    for (int i = 0; i < 64; ++i) {
        float a = sc[i], c = sc[64 + i];
        e0 = fmaf(__ldg(cwA + 2 * i), a, e0);
        e0 = fmaf(__ldg(cwA + 2 * i + 1), c, e0);
        e1 = fmaf(__ldg(cwB + 2 * i), a, e1);
        e1 = fmaf(__ldg(cwB + 2 * i + 1), c, e1);
    }
    __syncwarp();
    sc[o0] = e0; sc[o1] = e1;                      // combined[0..63] = emb
    #pragma unroll
    for (int k = 0; k < 4; ++k) {
        int j = lane * 4 + k;
        sc[64 + j] = zs[j][warp];                  // combined[64..191] = z[:,b]
    }
    __syncwarp();

    // hidden[e] = relu(W1[e,:] . combined + b1[e]), lane == e
    float hs = b1[lane];
    #pragma unroll 8
    for (int j = 0; j < 192; ++j)
        hs = fmaf(W1s[j * 32 + lane], sc[j], hs);
    hs = fmaxf(hs, 0.f);

    float o2 = b2[lane];
    #pragma unroll
    for (int j = 0; j < 32; ++j)
        o2 = fmaf(W2s[j * 32 + lane], __shfl_sync(0xffffffffu, hs, j), o2);

    // expert softmax over lanes
    float lg = -o2 * invT2;
    float mx = lg;
    mx = fmaxf(mx, __shfl_xor_sync(0xffffffffu, mx, 16));
    mx = fmaxf(mx, __shfl_xor_sync(0xffffffffu, mx, 8));
    mx = fmaxf(mx, __shfl_xor_sync(0xffffffffu, mx, 4));
    mx = fmaxf(mx, __shfl_xor_sync(0xffffffffu, mx, 2));
    mx = fmaxf(mx, __shfl_xor_sync(0xffffffffu, mx, 1));
    float pw2 = __expf(lg - mx);
    float sm2 = pw2;
    sm2 += __shfl_xor_sync(0xffffffffu, sm2, 16);
    sm2 += __shfl_xor_sync(0xffffffffu, sm2, 8);
    sm2 += __shfl_xor_sync(0xffffffffu, sm2, 4);
    sm2 += __shfl_xor_sync(0xffffffffu, sm2, 2);
    sm2 += __shfl_xor_sync(0xffffffffu, sm2, 1);
    g_w[(size_t)b * 32 + lane] = pw2 / sm2;
}

// ---------------- Kernel B: MoE mixture GEMM, k-split + FFMA2 ----------------
// out[m,b] += sum_{e in half,k} Wx[e,m,k]*w[e,b]*zcat[k,b]  (+ epilogue terms on split 0)
#define K3_BT 64
#define K3_MT 64
#define K3_THREADS 128
#define K3_CHUNKS 64            // chunks per k-split (128 total / 2 splits)

__global__ __launch_bounds__(K3_THREADS, 4)
void k_mix(const float* __restrict__ z, const float* __restrict__ Wx,
           const float* __restrict__ Amat, const float* __restrict__ hmat,
           float* __restrict__ out)
{
    __shared__ __align__(16) float Ws[2][32][68];   // [stage][k][m]   17.4 KB
    __shared__ __align__(16) float Vs[2][32][68];   // [stage][k][b]   17.4 KB
    __shared__ __align__(16) float w_s[32][68];     // [e][b]           8.7 KB

    int tid = threadIdx.x;
    int b0 = blockIdx.x * K3_BT;
    int m0 = blockIdx.y * K3_MT;
    int ks = blockIdx.z;                 // k-split: e in [ks*16, ks*16+16)
    int tx = tid & 7;                    // 8 groups of 8 b
    int ty = tid >> 3;                   // 16 groups of 4 m
    int tx8 = tx * 8, ty4 = ty * 4;

    // ---- stage expert-weight tile w_s[e][b] ----
    #pragma unroll
    for (int r = 0; r < 16; ++r) {
        int idx = tid + r * K3_THREADS;  // 0..2047
        int bb = idx >> 5, e = idx & 31;
        w_s[e][bb] = g_w[(size_t)(b0 + bb) * 32 + e];
    }
    __syncthreads();

    ull acc[4][4];                       // [m][b-pair] packed f32x2
    #pragma unroll
    for (int i = 0; i < 4; ++i)
        #pragma unroll
        for (int j = 0; j < 4; ++j) acc[i][j] = 0ull;

    float4 rW[4], rV[4];

    // ---- prefetch + stage chunk 0 ----
    {
        int g = ks * K3_CHUNKS;          // global chunk
        int e = g >> 2, k0 = (g & 3) << 5;
        const float* wxb = Wx + (size_t)e * (Mdim * Mdim) + (size_t)m0 * Mdim + k0;
        #pragma unroll
        for (int r = 0; r < 4; ++r) {
            int q = tid + r * K3_THREADS;          // 0..511
            int mm = q >> 3, kq = q & 7;
            rW[r] = *reinterpret_cast<const float4*>(wxb + (size_t)mm * Mdim + kq * 4);
        }
        #pragma unroll
        for (int r = 0; r < 4; ++r) {
            int idx = tid + r * K3_THREADS;        // 0..511
            int kk = idx >> 4, bq = (idx & 15) * 4;
            rV[r] = *reinterpret_cast<const float4*>(z + (size_t)(k0 + kk) * Bdim + b0 + bq);
        }
        #pragma unroll
        for (int r = 0; r < 4; ++r) {
            int q = tid + r * K3_THREADS;
            int mm = q >> 3, kq = q & 7;
            Ws[0][kq * 4 + 0][mm] = rW[r].x;
            Ws[0][kq * 4 + 1][mm] = rW[r].y;
            Ws[0][kq * 4 + 2][mm] = rW[r].z;
            Ws[0][kq * 4 + 3][mm] = rW[r].w;
        }
        #pragma unroll
        for (int r = 0; r < 4; ++r) {
            int idx = tid + r * K3_THREADS;
            int kk = idx >> 4, bq = (idx & 15) * 4;
            int kg = k0 + kk;
            float4 v = rV[r];
            if (kg >= Mdim - 2) {
                v.x = fmaxf(v.x, 0.f); v.y = fmaxf(v.y, 0.f);
                v.z = fmaxf(v.z, 0.f); v.w = fmaxf(v.w, 0.f);
            }
            float4 wq = *reinterpret_cast<const float4*>(&w_s[e][bq]);
            v.x *= wq.x; v.y *= wq.y; v.z *= wq.z; v.w *= wq.w;
            *reinterpret_cast<float4*>(&Vs[0][kk][bq]) = v;
        }
    }
    __syncthreads();

    // ---- main loop over 64 chunks, double-buffered, 1 sync/chunk ----
    for (int c = 0; c < K3_CHUNKS; ++c) {
        int s = c & 1;
        int en = 0, k0n = 0;
        if (c < K3_CHUNKS - 1) {
            int g = ks * K3_CHUNKS + c + 1;
            en = g >> 2; k0n = (g & 3) << 5;
            const float* wxb = Wx + (size_t)en * (Mdim * Mdim) + (size_t)m0 * Mdim + k0n;
            #pragma unroll
            for (int r = 0; r < 4; ++r) {
                int q = tid + r * K3_THREADS;
                int mm = q >> 3, kq = q & 7;
                rW[r] = *reinterpret_cast<const float4*>(wxb + (size_t)mm * Mdim + kq * 4);
            }
            #pragma unroll
            for (int r = 0; r < 4; ++r) {
                int idx = tid + r * K3_THREADS;
                int kk = idx >> 4, bq = (idx & 15) * 4;
                rV[r] = *reinterpret_cast<const float4*>(z + (size_t)(k0n + kk) * Bdim + b0 + bq);
            }
        }

        // compute on stage s
        #pragma unroll
        for (int kk = 0; kk < 32; ++kk) {
            float4 wv = *reinterpret_cast<const float4*>(&Ws[s][kk][ty4]);
            ulonglong2 va = *reinterpret_cast<const ulonglong2*>(&Vs[s][kk][tx8]);
            ulonglong2 vb = *reinterpret_cast<const ulonglong2*>(&Vs[s][kk][tx8 + 4]);
            ull w0 = bcast2(wv.x), w1 = bcast2(wv.y), w2 = bcast2(wv.z), w3 = bcast2(wv.w);
            fma2(acc[0][0], w0, va.x); fma2(acc[0][1], w0, va.y);
            fma2(acc[0][2], w0, vb.x); fma2(acc[0][3], w0, vb.y);
            fma2(acc[1][0], w1, va.x); fma2(acc[1][1], w1, va.y);
            fma2(acc[1][2], w1, vb.x); fma2(acc[1][3], w1, vb.y);
            fma2(acc[2][0], w2, va.x); fma2(acc[2][1], w2, va.y);
            fma2(acc[2][2], w2, vb.x); fma2(acc[2][3], w2, vb.y);
            fma2(acc[3][0], w3, va.x); fma2(acc[3][1], w3, va.y);
            fma2(acc[3][2], w3, vb.x); fma2(acc[3][3], w3, vb.y);
        }

        if (c < K3_CHUNKS - 1) {
            int sn = (c + 1) & 1;
            #pragma unroll
            for (int r = 0; r < 4; ++r) {
                int q = tid + r * K3_THREADS;
                int mm = q >> 3, kq = q & 7;
                Ws[sn][kq * 4 + 0][mm] = rW[r].x;
                Ws[sn][kq * 4 + 1][mm] = rW[r].y;
                Ws[sn][kq * 4 + 2][mm] = rW[r].z;
                Ws[sn][kq * 4 + 3][mm] = rW[r].w;
            }
            #pragma unroll
            for (int r = 0; r < 4; ++r) {
                int idx = tid + r * K3_THREADS;
                int kk = idx >> 4, bq = (idx & 15) * 4;
                int kg = k0n + kk;
                float4 v = rV[r];
                if (kg >= Mdim - 2) {
                    v.x = fmaxf(v.x, 0.f); v.y = fmaxf(v.y, 0.f);
                    v.z = fmaxf(v.z, 0.f); v.w = fmaxf(v.w, 0.f);
                }
                float4 wq = *reinterpret_cast<const float4*>(&w_s[en][bq]);
                v.x *= wq.x; v.y *= wq.y; v.z *= wq.z; v.w *= wq.w;
                *reinterpret_cast<float4*>(&Vs[sn][kk][bq]) = v;
            }
        }
        __syncthreads();
    }

    // ---- epilogue ----
    if (ks == 0) {
        // add h^T w into acc; build aA = A^T w
        ull aA[4][4];
        #pragma unroll
        for (int i = 0; i < 4; ++i)
            #pragma unroll
            for (int j = 0; j < 4; ++j) aA[i][j] = 0ull;

        #pragma unroll 4
        for (int e = 0; e < 32; ++e) {
            float4 hv = *reinterpret_cast<const float4*>(hmat + (size_t)e * Mdim + m0 + ty4);
            float4 av = *reinterpret_cast<const float4*>(Amat + (size_t)e * Mdim + m0 + ty4);
            ulonglong2 wa = *reinterpret_cast<const ulonglong2*>(&w_s[e][tx8]);
            ulonglong2 wb = *reinterpret_cast<const ulonglong2*>(&w_s[e][tx8 + 4]);
            ull h0 = bcast2(hv.x), h1 = bcast2(hv.y), h2 = bcast2(hv.z), h3 = bcast2(hv.w);
            ull a0 = bcast2(av.x), a1 = bcast2(av.y), a2 = bcast2(av.z), a3 = bcast2(av.w);
            fma2(acc[0][0], h0, wa.x); fma2(acc[0][1], h0, wa.y); fma2(acc[0][2], h0, wb.x); fma2(acc[0][3], h0, wb.y);
            fma2(acc[1][0], h1, wa.x); fma2(acc[1][1], h1, wa.y); fma2(acc[1][2], h1, wb.x); fma2(acc[1][3], h1, wb.y);
            fma2(acc[2][0], h2, wa.x); fma2(acc[2][1], h2, wa.y); fma2(acc[2][2], h2, wb.x); fma2(acc[2][3], h2, wb.y);
            fma2(acc[3][0], h3, wa.x); fma2(acc[3][1], h3, wa.y); fma2(acc[3][2], h3, wb.x); fma2(acc[3][3], h3, wb.y);
            fma2(aA[0][0], a0, wa.x); fma2(aA[0][1], a0, wa.y); fma2(aA[0][2], a0, wb.x); fma2(aA[0][3], a0, wb.y);
            fma2(aA[1][0], a1, wa.x); fma2(aA[1][1], a1, wa.y); fma2(aA[1][2], a1, wb.x); fma2(aA[1][3], a1, wb.y);
            fma2(aA[2][0], a2, wa.x); fma2(aA[2][1], a2, wa.y); fma2(aA[2][2], a2, wb.x); fma2(aA[2][3], a2, wb.y);
            fma2(aA[3][0], a3, wa.x); fma2(aA[3][1], a3, wa.y); fma2(aA[3][2], a3, wb.x); fma2(aA[3][3], a3, wb.y);
        }

        #pragma unroll
        for (int i = 0; i < 4; ++i) {
            int m = m0 + ty4 + i;
            float* op = out + (size_t)m * Bdim + b0 + tx8;
            const float* zp = z + (size_t)m * Bdim + b0 + tx8;
            float4 z0 = *reinterpret_cast<const float4*>(zp);
            float4 z1 = *reinterpret_cast<const float4*>(zp + 4);
            float2 g0 = unpack2(acc[i][0]); float2 g1 = unpack2(acc[i][1]);
            float2 g2 = unpack2(acc[i][2]); float2 g3 = unpack2(acc[i][3]);
            float2 q0 = unpack2(aA[i][0]);  float2 q1 = unpack2(aA[i][1]);
            float2 q2 = unpack2(aA[i][2]);  float2 q3 = unpack2(aA[i][3]);
            atomicAdd(op + 0, fmaf(z0.x, q0.x, g0.x));
            atomicAdd(op + 1, fmaf(z0.y, q0.y, g0.y));
            atomicAdd(op + 2, fmaf(z0.z, q1.x, g1.x));
            atomicAdd(op + 3, fmaf(z0.w, q1.y, g1.y));
            atomicAdd(op + 4, fmaf(z1.x, q2.x, g2.x));
            atomicAdd(op + 5, fmaf(z1.y, q2.y, g2.y));
            atomicAdd(op + 6, fmaf(z1.z, q3.x, g3.x));
            atomicAdd(op + 7, fmaf(z1.w, q3.y, g3.y));
        }
    } else {
        #pragma unroll
        for (int i = 0; i < 4; ++i) {
            int m = m0 + ty4 + i;
            float* op = out + (size_t)m * Bdim + b0 + tx8;
            float2 g0 = unpack2(acc[i][0]); float2 g1 = unpack2(acc[i][1]);
            float2 g2 = unpack2(acc[i][2]); float2 g3 = unpack2(acc[i][3]);
            atomicAdd(op + 0, g0.x);
            atomicAdd(op + 1, g0.y);
            atomicAdd(op + 2, g1.x);
            atomicAdd(op + 3, g1.y);
            atomicAdd(op + 4, g2.x);
            atomicAdd(op + 5, g2.y);
            atomicAdd(op + 6, g3.x);
            atomicAdd(op + 7, g3.y);
        }
    }
}

// ---------------- launch ----------------
extern "C" void kernel_launch(void* const* d_in, const int* in_sizes, int n_in,
                              void* d_out, int out_size)
{
    const float* z       = (const float*)d_in[0];
    const float* ctx     = (const float*)d_in[1];
    const float* noise   = (const float*)d_in[2];
    const float* conv_w  = (const float*)d_in[3];
    const float* conv_b  = (const float*)d_in[4];
    const float* Dm      = (const float*)d_in[5];
    const float* sigma_g = (const float*)d_in[6];
    const float* temp1   = (const float*)d_in[7];
    const float* W1      = (const float*)d_in[8];
    const float* b1      = (const float*)d_in[9];
    const float* W2      = (const float*)d_in[10];
    const float* b2      = (const float*)d_in[11];
    const float* temp2   = (const float*)d_in[12];
    const float* Amat    = (const float*)d_in[13];
    const float* Wx      = (const float*)d_in[14];
    const float* hmat    = (const float*)d_in[15];
    float* out = (float*)d_out;

    k_zero<<<(Mdim * Bdim / 4) / 256, 256>>>(out);
    k_attn<<<Bdim / K2_WARPS, 256>>>(ctx, z, noise, Dm, sigma_g,
                                     conv_w, conv_b, temp1, W1, b1, W2, b2, temp2);
    k_mix<<<dim3(Bdim / K3_BT, Mdim / K3_MT, 2), K3_THREADS>>>(z, Wx, Amat, hmat, out);
}